// round 10
// baseline (speedup 1.0000x reference)
#include <cuda_runtime.h>

// DirectVoxGO volume rendering composite, R7: 2 warps per ray.
//   log2(1-alpha_i) = -interval * log2(1 + exp(density_i + shift))
//   w_i = P_{i-1} - P_i,  P = 2^(per-ray inclusive prefix of log2(1-alpha))
//   out[r] = sum w_i rgb_i + P_last * bg
// Ray split in half; halves are independent (transmittance factorizes):
//   rgb = rgbA + 2^totA * rgbB,  Tlast = 2^(totA+totB)
//
// Kernel 1: offsets table, 16 elements/thread (4 x int4), prev via shfl.
// Kernel 2: two warps per ray, 4 samples/thread, all LDG.128, smem combine.

#define MAX_RAYS ((1 << 20))
__device__ int g_offsets[MAX_RAYS + 2];

__device__ __forceinline__ float f_ex2(float x) {
    float y; asm("ex2.approx.ftz.f32 %0, %1;" : "=f"(y) : "f"(x)); return y;
}
__device__ __forceinline__ float f_lg2(float x) {
    float y; asm("lg2.approx.ftz.f32 %0, %1;" : "=f"(y) : "f"(x)); return y;
}

// ---- Phase 1: offsets table, 16 elements per thread ----
__global__ void __launch_bounds__(256)
build_offsets_vec16(const int* __restrict__ ray_id, int M, int n_rays) {
    const int t  = blockIdx.x * blockDim.x + threadIdx.x;
    const int e0 = t * 16;
    const bool full = (e0 + 15 < M);

    int4 v0 = make_int4(0,0,0,0), v1 = v0, v2 = v0, v3 = v0;
    if (full) {
        const int4* p = reinterpret_cast<const int4*>(ray_id) + t * 4;
        v0 = p[0]; v1 = p[1]; v2 = p[2]; v3 = p[3];
    }
    const int prevw = __shfl_up_sync(0xffffffffu, v3.w, 1);

    if (e0 >= M) return;

    if (!full) {                          // scalar tail (generic-M safety)
        int prev = (e0 == 0) ? -1 : __ldg(&ray_id[e0 - 1]);
        for (int i = e0; i < M; ++i) {
            int cur = __ldg(&ray_id[i]);
            for (int r = prev + 1; r <= cur; ++r) g_offsets[r] = i;
            prev = cur;
        }
        for (int r = prev + 1; r <= n_rays; ++r) g_offsets[r] = M;
        return;
    }

    int prev;
    if ((threadIdx.x & 31) == 0 || e0 == 0)
        prev = (e0 == 0) ? -1 : __ldg(&ray_id[e0 - 1]);
    else
        prev = prevw;

    const int vals[16] = {v0.x, v0.y, v0.z, v0.w,  v1.x, v1.y, v1.z, v1.w,
                          v2.x, v2.y, v2.z, v2.w,  v3.x, v3.y, v3.z, v3.w};
    #pragma unroll
    for (int j = 0; j < 16; ++j) {
        const int cur = vals[j];
        if (cur != prev) {
            for (int r = prev + 1; r <= cur; ++r) g_offsets[r] = e0 + j;
        }
        prev = cur;
    }
    if (e0 + 15 == M - 1) {
        for (int r = prev + 1; r <= n_rays; ++r) g_offsets[r] = M;
    }
}

// ---- Phase 2: two warps per ray, 4 samples/thread ----
__global__ void __launch_bounds__(256)
composite_kernel(const float* __restrict__ density,
                 const float* __restrict__ rgb,
                 const float* __restrict__ bg,
                 const float* __restrict__ p_shift,
                 const float* __restrict__ p_interval,
                 float* __restrict__ out,
                 int n_rays) {
    __shared__ float4 s_part[8];          // per-warp partial (ar,ag,ab,tot)

    const int wid   = threadIdx.x >> 5;   // warp in block (0..7)
    const int lane  = threadIdx.x & 31;
    const int gwarp = blockIdx.x * 8 + wid;
    const int ray   = gwarp >> 1;         // 2 warps per ray
    const int half  = gwarp & 1;
    const bool live = (ray < n_rays);

    float carry = 0.f;                    // log2(T) across this half
    float ar = 0.f, ag = 0.f, ab = 0.f;

    if (live) {
        const int rs = g_offsets[ray];
        const int re = g_offsets[ray + 1];
        // 4-aligned midpoint split
        int mid = (rs + ((re - rs + 1) >> 1) + 3) & ~3;
        if (mid > re) mid = re;
        if (mid < rs) mid = rs;

        const int start = half ? mid : rs;
        const int end   = half ? re  : mid;
        const unsigned seglen = (unsigned)(end - start);

        const float shift = *p_shift;
        const float nInterval = -(*p_interval);
        const float L2E = 1.4426950408889634f;

        for (int base = (start & ~3); base < end; base += 128) {
            const int idx0 = base + lane * 4;
            const bool grp = (idx0 < end);

            float4 d  = make_float4(0.f, 0.f, 0.f, 0.f);
            float4 c0 = d, c1 = d, c2 = d;
            if (grp) {
                d  = *reinterpret_cast<const float4*>(density + idx0);
                const float* cbase = rgb + 3 * idx0;              // 16B aligned
                c0 = *reinterpret_cast<const float4*>(cbase);
                c1 = *reinterpret_cast<const float4*>(cbase + 4);
                c2 = *reinterpret_cast<const float4*>(cbase + 8);
            }

            // per-element log2(1-alpha); 0 outside [start, end)
            float dv[4] = {d.x, d.y, d.z, d.w};
            float l2t[4];
            #pragma unroll
            for (int j = 0; j < 4; ++j) {
                const bool in = (unsigned)(idx0 + j - start) < seglen;
                if (in) {
                    float e = f_ex2((dv[j] + shift) * L2E);   // exp(x)
                    l2t[j] = nInterval * f_lg2(1.f + e);      // <= 0
                } else {
                    l2t[j] = 0.f;
                }
            }

            const float s0 = l2t[0];
            const float s1 = s0 + l2t[1];
            const float s2 = s1 + l2t[2];
            const float s3 = s2 + l2t[3];

            float inc = s3;
            #pragma unroll
            for (int off = 1; off < 32; off <<= 1) {
                float v = __shfl_up_sync(0xffffffffu, inc, off);
                if (lane >= off) inc += v;
            }
            const float excl = carry + (inc - s3);

            const float Pm1 = f_ex2(excl);
            const float P0  = f_ex2(excl + s0);
            const float P1  = f_ex2(excl + s1);
            const float P2  = f_ex2(excl + s2);
            const float P3  = f_ex2(excl + s3);

            const float w0 = Pm1 - P0;
            const float w1 = P0 - P1;
            const float w2 = P1 - P2;
            const float w3 = P2 - P3;

            ar = fmaf(w0, c0.x, ar);  ag = fmaf(w0, c0.y, ag);  ab = fmaf(w0, c0.z, ab);
            ar = fmaf(w1, c0.w, ar);  ag = fmaf(w1, c1.x, ag);  ab = fmaf(w1, c1.y, ab);
            ar = fmaf(w2, c1.z, ar);  ag = fmaf(w2, c1.w, ag);  ab = fmaf(w2, c2.x, ab);
            ar = fmaf(w3, c2.y, ar);  ag = fmaf(w3, c2.z, ag);  ab = fmaf(w3, c2.w, ab);

            carry += __shfl_sync(0xffffffffu, inc, 31);
        }

        // warp reduction of rgb partials
        #pragma unroll
        for (int off = 16; off; off >>= 1) {
            ar += __shfl_xor_sync(0xffffffffu, ar, off);
            ag += __shfl_xor_sync(0xffffffffu, ag, off);
            ab += __shfl_xor_sync(0xffffffffu, ab, off);
        }
    }

    if (lane == 0) s_part[wid] = make_float4(ar, ag, ab, carry);
    __syncthreads();

    // even warp of each pair combines and writes
    if (live && half == 0 && lane == 0) {
        const float4 A = s_part[wid];
        const float4 B = s_part[wid + 1];
        const float TA = f_ex2(A.w);
        const float Tlast = f_ex2(A.w + B.w);
        out[3 * ray + 0] = fmaf(TA, B.x, A.x) + Tlast * bg[0];
        out[3 * ray + 1] = fmaf(TA, B.y, A.y) + Tlast * bg[1];
        out[3 * ray + 2] = fmaf(TA, B.z, A.z) + Tlast * bg[2];
    }
}

extern "C" void kernel_launch(void* const* d_in, const int* in_sizes, int n_in,
                              void* d_out, int out_size) {
    const float* density    = (const float*)d_in[0];
    const float* rgb        = (const float*)d_in[1];
    const float* bg         = (const float*)d_in[2];
    const float* p_shift    = (const float*)d_in[3];
    const float* p_interval = (const float*)d_in[4];
    const int*   ray_id     = (const int*)d_in[5];

    const int M      = in_sizes[0];
    const int n_rays = out_size / 3;
    float* out = (float*)d_out;

    {
        const int nthreads16 = (M + 15) / 16;
        const int blocks = (nthreads16 + 255) / 256;
        build_offsets_vec16<<<blocks, 256>>>(ray_id, M, n_rays);
    }
    {
        const int blocks = (n_rays * 2 * 32 + 255) / 256;   // 4 rays per block
        composite_kernel<<<blocks, 256>>>(density, rgb, bg, p_shift,
                                          p_interval, out, n_rays);
    }
}

// round 12
// speedup vs baseline: 1.0819x; 1.0819x over previous
#include <cuda_runtime.h>

// DirectVoxGO volume rendering composite, R8: R6 skeleton + software pipeline.
//   log2(1-alpha_i) = -interval * log2(1 + exp(density_i + shift))
//   w_i = P_{i-1} - P_i,  P = 2^(per-ray inclusive prefix of log2(1-alpha))
//   out[r] = sum w_i rgb_i + P_last * bg
//
// Kernel 1: offsets table, 16 elements/thread (4 x int4), prev via shfl.
// Kernel 2: one warp per ray, 4 samples/thread, all LDG.128.
//           Density of chunk k+1 prefetched during chunk k's scan;
//           rgb loads issued before the scan, consumed after it.

#define MAX_RAYS ((1 << 20))
__device__ int g_offsets[MAX_RAYS + 2];

__device__ __forceinline__ float f_ex2(float x) {
    float y; asm("ex2.approx.ftz.f32 %0, %1;" : "=f"(y) : "f"(x)); return y;
}
__device__ __forceinline__ float f_lg2(float x) {
    float y; asm("lg2.approx.ftz.f32 %0, %1;" : "=f"(y) : "f"(x)); return y;
}

// ---- Phase 1: offsets table, 16 elements per thread ----
__global__ void __launch_bounds__(256)
build_offsets_vec16(const int* __restrict__ ray_id, int M, int n_rays) {
    const int t  = blockIdx.x * blockDim.x + threadIdx.x;
    const int e0 = t * 16;
    const bool full = (e0 + 15 < M);

    int4 v0 = make_int4(0,0,0,0), v1 = v0, v2 = v0, v3 = v0;
    if (full) {
        const int4* p = reinterpret_cast<const int4*>(ray_id) + t * 4;
        v0 = p[0]; v1 = p[1]; v2 = p[2]; v3 = p[3];
    }
    const int prevw = __shfl_up_sync(0xffffffffu, v3.w, 1);

    if (e0 >= M) return;

    if (!full) {                          // scalar tail (generic-M safety)
        int prev = (e0 == 0) ? -1 : __ldg(&ray_id[e0 - 1]);
        for (int i = e0; i < M; ++i) {
            int cur = __ldg(&ray_id[i]);
            for (int r = prev + 1; r <= cur; ++r) g_offsets[r] = i;
            prev = cur;
        }
        for (int r = prev + 1; r <= n_rays; ++r) g_offsets[r] = M;
        return;
    }

    int prev;
    if ((threadIdx.x & 31) == 0 || e0 == 0)
        prev = (e0 == 0) ? -1 : __ldg(&ray_id[e0 - 1]);
    else
        prev = prevw;

    const int vals[16] = {v0.x, v0.y, v0.z, v0.w,  v1.x, v1.y, v1.z, v1.w,
                          v2.x, v2.y, v2.z, v2.w,  v3.x, v3.y, v3.z, v3.w};
    #pragma unroll
    for (int j = 0; j < 16; ++j) {
        const int cur = vals[j];
        if (cur != prev) {
            for (int r = prev + 1; r <= cur; ++r) g_offsets[r] = e0 + j;
        }
        prev = cur;
    }
    if (e0 + 15 == M - 1) {
        for (int r = prev + 1; r <= n_rays; ++r) g_offsets[r] = M;
    }
}

// ---- Phase 2: one warp per ray, 4 samples/thread, pipelined ----
__global__ void __launch_bounds__(256)
composite_kernel(const float* __restrict__ density,
                 const float* __restrict__ rgb,
                 const float* __restrict__ bg,
                 const float* __restrict__ p_shift,
                 const float* __restrict__ p_interval,
                 float* __restrict__ out,
                 int n_rays) {
    const int warp = (blockIdx.x * blockDim.x + threadIdx.x) >> 5;
    const int lane = threadIdx.x & 31;
    if (warp >= n_rays) return;

    const int start = g_offsets[warp];
    const int end   = g_offsets[warp + 1];
    const unsigned seglen = (unsigned)(end - start);

    const float shift = *p_shift;
    const float nInterval = -(*p_interval);
    const float L2E = 1.4426950408889634f;

    float carry = 0.f;                 // running log2(T) at chunk entry
    float ar = 0.f, ag = 0.f, ab = 0.f;

    const int base0 = start & ~3;      // idx = base + lane*4 stays 4-aligned

    // prologue: density for first chunk
    float4 d = make_float4(0.f, 0.f, 0.f, 0.f);
    {
        const int idx0 = base0 + lane * 4;
        if (idx0 < end) d = *reinterpret_cast<const float4*>(density + idx0);
    }

    for (int base = base0; base < end; base += 128) {
        const int idx0 = base + lane * 4;
        const bool grp = (idx0 < end);

        // rgb loads issued up front; consumed after the scan (latency hidden)
        float4 c0 = make_float4(0.f, 0.f, 0.f, 0.f), c1 = c0, c2 = c0;
        if (grp) {
            const float* cbase = rgb + 3 * idx0;                  // 16B aligned
            c0 = *reinterpret_cast<const float4*>(cbase);
            c1 = *reinterpret_cast<const float4*>(cbase + 4);
            c2 = *reinterpret_cast<const float4*>(cbase + 8);
        }

        // per-element log2(1-alpha); 0 outside [start, end)
        const float dv[4] = {d.x, d.y, d.z, d.w};
        float l2t[4];
        #pragma unroll
        for (int j = 0; j < 4; ++j) {
            const bool in = (unsigned)(idx0 + j - start) < seglen;
            if (in) {
                float e = f_ex2((dv[j] + shift) * L2E);       // exp(x)
                l2t[j] = nInterval * f_lg2(1.f + e);          // <= 0
            } else {
                l2t[j] = 0.f;
            }
        }

        // prefetch next chunk's density while the scan runs
        {
            const int nidx0 = base + 128 + lane * 4;
            float4 dn = make_float4(0.f, 0.f, 0.f, 0.f);
            if (nidx0 < end) dn = *reinterpret_cast<const float4*>(density + nidx0);
            d = dn;
        }

        // thread-local inclusive prefix
        const float s0 = l2t[0];
        const float s1 = s0 + l2t[1];
        const float s2 = s1 + l2t[2];
        const float s3 = s2 + l2t[3];

        // warp scan of thread totals
        float inc = s3;
        #pragma unroll
        for (int off = 1; off < 32; off <<= 1) {
            float v = __shfl_up_sync(0xffffffffu, inc, off);
            if (lane >= off) inc += v;
        }
        const float excl = carry + (inc - s3);

        // transmittance samples; identical exponents => exact zero weights
        const float Pm1 = f_ex2(excl);
        const float P0  = f_ex2(excl + s0);
        const float P1  = f_ex2(excl + s1);
        const float P2  = f_ex2(excl + s2);
        const float P3  = f_ex2(excl + s3);

        const float w0 = Pm1 - P0;
        const float w1 = P0 - P1;
        const float w2 = P1 - P2;
        const float w3 = P2 - P3;

        // rgb layout: c0=(r0,g0,b0,r1) c1=(g1,b1,r2,g2) c2=(b2,r3,g3,b3)
        ar = fmaf(w0, c0.x, ar);  ag = fmaf(w0, c0.y, ag);  ab = fmaf(w0, c0.z, ab);
        ar = fmaf(w1, c0.w, ar);  ag = fmaf(w1, c1.x, ag);  ab = fmaf(w1, c1.y, ab);
        ar = fmaf(w2, c1.z, ar);  ag = fmaf(w2, c1.w, ag);  ab = fmaf(w2, c2.x, ab);
        ar = fmaf(w3, c2.y, ar);  ag = fmaf(w3, c2.z, ag);  ab = fmaf(w3, c2.w, ab);

        carry += __shfl_sync(0xffffffffu, inc, 31);
    }

    // warp reduction
    #pragma unroll
    for (int off = 16; off; off >>= 1) {
        ar += __shfl_xor_sync(0xffffffffu, ar, off);
        ag += __shfl_xor_sync(0xffffffffu, ag, off);
        ab += __shfl_xor_sync(0xffffffffu, ab, off);
    }

    if (lane == 0) {
        const float Tlast = f_ex2(carry);
        out[3 * warp + 0] = ar + Tlast * bg[0];
        out[3 * warp + 1] = ag + Tlast * bg[1];
        out[3 * warp + 2] = ab + Tlast * bg[2];
    }
}

extern "C" void kernel_launch(void* const* d_in, const int* in_sizes, int n_in,
                              void* d_out, int out_size) {
    const float* density    = (const float*)d_in[0];
    const float* rgb        = (const float*)d_in[1];
    const float* bg         = (const float*)d_in[2];
    const float* p_shift    = (const float*)d_in[3];
    const float* p_interval = (const float*)d_in[4];
    const int*   ray_id     = (const int*)d_in[5];

    const int M      = in_sizes[0];
    const int n_rays = out_size / 3;
    float* out = (float*)d_out;

    {
        const int nthreads16 = (M + 15) / 16;
        const int blocks = (nthreads16 + 255) / 256;
        build_offsets_vec16<<<blocks, 256>>>(ray_id, M, n_rays);
    }
    {
        const int blocks = (n_rays * 32 + 255) / 256;   // 8 rays per block
        composite_kernel<<<blocks, 256>>>(density, rgb, bg, p_shift,
                                          p_interval, out, n_rays);
    }
}

// round 13
// speedup vs baseline: 1.0919x; 1.0093x over previous
#include <cuda_runtime.h>

// DirectVoxGO volume rendering composite, R9: R6 skeleton, occupancy bumped.
//   log2(1-alpha_i) = -interval * log2(1 + exp(density_i + shift))
//   w_i = P_{i-1} - P_i,  P = 2^(per-ray inclusive prefix of log2(1-alpha))
//   out[r] = sum w_i rgb_i + P_last * bg
//
// Kernel 1: offsets table, 16 elements/thread (4 x int4), prev via shfl.
// Kernel 2: one warp per ray, 4 samples/thread, all LDG.128.
//           __launch_bounds__(256,7) caps regs at 36 -> 7 blocks/SM (56 warps).

#define MAX_RAYS ((1 << 20))
__device__ int g_offsets[MAX_RAYS + 2];

__device__ __forceinline__ float f_ex2(float x) {
    float y; asm("ex2.approx.ftz.f32 %0, %1;" : "=f"(y) : "f"(x)); return y;
}
__device__ __forceinline__ float f_lg2(float x) {
    float y; asm("lg2.approx.ftz.f32 %0, %1;" : "=f"(y) : "f"(x)); return y;
}

// ---- Phase 1: offsets table, 16 elements per thread ----
__global__ void __launch_bounds__(256)
build_offsets_vec16(const int* __restrict__ ray_id, int M, int n_rays) {
    const int t  = blockIdx.x * blockDim.x + threadIdx.x;
    const int e0 = t * 16;
    const bool full = (e0 + 15 < M);

    int4 v0 = make_int4(0,0,0,0), v1 = v0, v2 = v0, v3 = v0;
    if (full) {
        const int4* p = reinterpret_cast<const int4*>(ray_id) + t * 4;
        v0 = p[0]; v1 = p[1]; v2 = p[2]; v3 = p[3];
    }
    const int prevw = __shfl_up_sync(0xffffffffu, v3.w, 1);

    if (e0 >= M) return;

    if (!full) {                          // scalar tail (generic-M safety)
        int prev = (e0 == 0) ? -1 : __ldg(&ray_id[e0 - 1]);
        for (int i = e0; i < M; ++i) {
            int cur = __ldg(&ray_id[i]);
            for (int r = prev + 1; r <= cur; ++r) g_offsets[r] = i;
            prev = cur;
        }
        for (int r = prev + 1; r <= n_rays; ++r) g_offsets[r] = M;
        return;
    }

    int prev;
    if ((threadIdx.x & 31) == 0 || e0 == 0)
        prev = (e0 == 0) ? -1 : __ldg(&ray_id[e0 - 1]);
    else
        prev = prevw;

    const int vals[16] = {v0.x, v0.y, v0.z, v0.w,  v1.x, v1.y, v1.z, v1.w,
                          v2.x, v2.y, v2.z, v2.w,  v3.x, v3.y, v3.z, v3.w};
    #pragma unroll
    for (int j = 0; j < 16; ++j) {
        const int cur = vals[j];
        if (cur != prev) {
            for (int r = prev + 1; r <= cur; ++r) g_offsets[r] = e0 + j;
        }
        prev = cur;
    }
    if (e0 + 15 == M - 1) {
        for (int r = prev + 1; r <= n_rays; ++r) g_offsets[r] = M;
    }
}

// ---- Phase 2: one warp per ray, 4 samples/thread, vectorized ----
__global__ void __launch_bounds__(256, 7)
composite_kernel(const float* __restrict__ density,
                 const float* __restrict__ rgb,
                 const float* __restrict__ bg,
                 const float* __restrict__ p_shift,
                 const float* __restrict__ p_interval,
                 float* __restrict__ out,
                 int n_rays) {
    const int warp = (blockIdx.x * blockDim.x + threadIdx.x) >> 5;
    const int lane = threadIdx.x & 31;
    if (warp >= n_rays) return;

    const int start = g_offsets[warp];
    const int end   = g_offsets[warp + 1];
    const unsigned seglen = (unsigned)(end - start);

    const float shift = *p_shift;
    const float nInterval = -(*p_interval);
    const float L2E = 1.4426950408889634f;

    float carry = 0.f;                 // running log2(T) at chunk entry
    float ar = 0.f, ag = 0.f, ab = 0.f;

    // aligned chunk base: idx0 = base + lane*4 is always 4-aligned -> LDG.128
    for (int base = (start & ~3); base < end; base += 128) {
        const int idx0 = base + lane * 4;
        const bool grp = (idx0 < end);

        float4 d  = make_float4(0.f, 0.f, 0.f, 0.f);
        float4 c0 = d, c1 = d, c2 = d;
        if (grp) {
            d  = *reinterpret_cast<const float4*>(density + idx0);
            const float* cbase = rgb + 3 * idx0;                  // 16B aligned
            c0 = *reinterpret_cast<const float4*>(cbase);
            c1 = *reinterpret_cast<const float4*>(cbase + 4);
            c2 = *reinterpret_cast<const float4*>(cbase + 8);
        }

        // per-element log2(1-alpha); 0 outside [start, end)
        float dv[4] = {d.x, d.y, d.z, d.w};
        float l2t[4];
        #pragma unroll
        for (int j = 0; j < 4; ++j) {
            // single unsigned compare covers idx>=start && idx<end
            const bool in = (unsigned)(idx0 + j - start) < seglen;
            if (in) {
                float e = f_ex2((dv[j] + shift) * L2E);       // exp(x)
                l2t[j] = nInterval * f_lg2(1.f + e);          // <= 0
            } else {
                l2t[j] = 0.f;
            }
        }

        // thread-local inclusive prefix
        const float s0 = l2t[0];
        const float s1 = s0 + l2t[1];
        const float s2 = s1 + l2t[2];
        const float s3 = s2 + l2t[3];

        // warp scan of thread totals
        float inc = s3;
        #pragma unroll
        for (int off = 1; off < 32; off <<= 1) {
            float v = __shfl_up_sync(0xffffffffu, inc, off);
            if (lane >= off) inc += v;
        }
        const float excl = carry + (inc - s3);

        // transmittance samples; identical exponents => exact zero weights
        const float Pm1 = f_ex2(excl);
        const float P0  = f_ex2(excl + s0);
        const float P1  = f_ex2(excl + s1);
        const float P2  = f_ex2(excl + s2);
        const float P3  = f_ex2(excl + s3);

        const float w0 = Pm1 - P0;
        const float w1 = P0 - P1;
        const float w2 = P1 - P2;
        const float w3 = P2 - P3;

        // rgb layout: c0=(r0,g0,b0,r1) c1=(g1,b1,r2,g2) c2=(b2,r3,g3,b3)
        ar = fmaf(w0, c0.x, ar);  ag = fmaf(w0, c0.y, ag);  ab = fmaf(w0, c0.z, ab);
        ar = fmaf(w1, c0.w, ar);  ag = fmaf(w1, c1.x, ag);  ab = fmaf(w1, c1.y, ab);
        ar = fmaf(w2, c1.z, ar);  ag = fmaf(w2, c1.w, ag);  ab = fmaf(w2, c2.x, ab);
        ar = fmaf(w3, c2.y, ar);  ag = fmaf(w3, c2.z, ag);  ab = fmaf(w3, c2.w, ab);

        carry += __shfl_sync(0xffffffffu, inc, 31);
    }

    // warp reduction
    #pragma unroll
    for (int off = 16; off; off >>= 1) {
        ar += __shfl_xor_sync(0xffffffffu, ar, off);
        ag += __shfl_xor_sync(0xffffffffu, ag, off);
        ab += __shfl_xor_sync(0xffffffffu, ab, off);
    }

    if (lane == 0) {
        const float Tlast = f_ex2(carry);
        out[3 * warp + 0] = ar + Tlast * bg[0];
        out[3 * warp + 1] = ag + Tlast * bg[1];
        out[3 * warp + 2] = ab + Tlast * bg[2];
    }
}

extern "C" void kernel_launch(void* const* d_in, const int* in_sizes, int n_in,
                              void* d_out, int out_size) {
    const float* density    = (const float*)d_in[0];
    const float* rgb        = (const float*)d_in[1];
    const float* bg         = (const float*)d_in[2];
    const float* p_shift    = (const float*)d_in[3];
    const float* p_interval = (const float*)d_in[4];
    const int*   ray_id     = (const int*)d_in[5];

    const int M      = in_sizes[0];
    const int n_rays = out_size / 3;
    float* out = (float*)d_out;

    {
        const int nthreads16 = (M + 15) / 16;
        const int blocks = (nthreads16 + 255) / 256;
        build_offsets_vec16<<<blocks, 256>>>(ray_id, M, n_rays);
    }
    {
        const int blocks = (n_rays * 32 + 255) / 256;   // 8 rays per block
        composite_kernel<<<blocks, 256>>>(density, rgb, bg, p_shift,
                                          p_interval, out, n_rays);
    }
}

// round 14
// speedup vs baseline: 1.1647x; 1.0667x over previous
#include <cuda_runtime.h>

// DirectVoxGO volume rendering composite, R10: R6 skeleton, 128-thread blocks.
//   log2(1-alpha_i) = -interval * log2(1 + exp(density_i + shift))
//   w_i = P_{i-1} - P_i,  P = 2^(per-ray inclusive prefix of log2(1-alpha))
//   out[r] = sum w_i rgb_i + P_last * bg
//
// Kernel 1: offsets table, 16 elements/thread (4 x int4), prev via shfl.
// Kernel 2: one warp per ray, 4 samples/thread, all LDG.128, 38 regs.
//           128-thread blocks: 13 blocks/SM -> 52 warps (vs 48 at 256 thr).

#define MAX_RAYS ((1 << 20))
__device__ int g_offsets[MAX_RAYS + 2];

__device__ __forceinline__ float f_ex2(float x) {
    float y; asm("ex2.approx.ftz.f32 %0, %1;" : "=f"(y) : "f"(x)); return y;
}
__device__ __forceinline__ float f_lg2(float x) {
    float y; asm("lg2.approx.ftz.f32 %0, %1;" : "=f"(y) : "f"(x)); return y;
}

// ---- Phase 1: offsets table, 16 elements per thread ----
__global__ void __launch_bounds__(256)
build_offsets_vec16(const int* __restrict__ ray_id, int M, int n_rays) {
    const int t  = blockIdx.x * blockDim.x + threadIdx.x;
    const int e0 = t * 16;
    const bool full = (e0 + 15 < M);

    int4 v0 = make_int4(0,0,0,0), v1 = v0, v2 = v0, v3 = v0;
    if (full) {
        const int4* p = reinterpret_cast<const int4*>(ray_id) + t * 4;
        v0 = p[0]; v1 = p[1]; v2 = p[2]; v3 = p[3];
    }
    const int prevw = __shfl_up_sync(0xffffffffu, v3.w, 1);

    if (e0 >= M) return;

    if (!full) {                          // scalar tail (generic-M safety)
        int prev = (e0 == 0) ? -1 : __ldg(&ray_id[e0 - 1]);
        for (int i = e0; i < M; ++i) {
            int cur = __ldg(&ray_id[i]);
            for (int r = prev + 1; r <= cur; ++r) g_offsets[r] = i;
            prev = cur;
        }
        for (int r = prev + 1; r <= n_rays; ++r) g_offsets[r] = M;
        return;
    }

    int prev;
    if ((threadIdx.x & 31) == 0 || e0 == 0)
        prev = (e0 == 0) ? -1 : __ldg(&ray_id[e0 - 1]);
    else
        prev = prevw;

    const int vals[16] = {v0.x, v0.y, v0.z, v0.w,  v1.x, v1.y, v1.z, v1.w,
                          v2.x, v2.y, v2.z, v2.w,  v3.x, v3.y, v3.z, v3.w};
    #pragma unroll
    for (int j = 0; j < 16; ++j) {
        const int cur = vals[j];
        if (cur != prev) {
            for (int r = prev + 1; r <= cur; ++r) g_offsets[r] = e0 + j;
        }
        prev = cur;
    }
    if (e0 + 15 == M - 1) {
        for (int r = prev + 1; r <= n_rays; ++r) g_offsets[r] = M;
    }
}

// ---- Phase 2: one warp per ray, 4 samples/thread, vectorized ----
__global__ void __launch_bounds__(128)
composite_kernel(const float* __restrict__ density,
                 const float* __restrict__ rgb,
                 const float* __restrict__ bg,
                 const float* __restrict__ p_shift,
                 const float* __restrict__ p_interval,
                 float* __restrict__ out,
                 int n_rays) {
    const int warp = (blockIdx.x * blockDim.x + threadIdx.x) >> 5;
    const int lane = threadIdx.x & 31;
    if (warp >= n_rays) return;

    const int start = g_offsets[warp];
    const int end   = g_offsets[warp + 1];
    const unsigned seglen = (unsigned)(end - start);

    const float shift = *p_shift;
    const float nInterval = -(*p_interval);
    const float L2E = 1.4426950408889634f;

    float carry = 0.f;                 // running log2(T) at chunk entry
    float ar = 0.f, ag = 0.f, ab = 0.f;

    // aligned chunk base: idx0 = base + lane*4 is always 4-aligned -> LDG.128
    for (int base = (start & ~3); base < end; base += 128) {
        const int idx0 = base + lane * 4;
        const bool grp = (idx0 < end);

        float4 d  = make_float4(0.f, 0.f, 0.f, 0.f);
        float4 c0 = d, c1 = d, c2 = d;
        if (grp) {
            d  = *reinterpret_cast<const float4*>(density + idx0);
            const float* cbase = rgb + 3 * idx0;                  // 16B aligned
            c0 = *reinterpret_cast<const float4*>(cbase);
            c1 = *reinterpret_cast<const float4*>(cbase + 4);
            c2 = *reinterpret_cast<const float4*>(cbase + 8);
        }

        // per-element log2(1-alpha); 0 outside [start, end)
        float dv[4] = {d.x, d.y, d.z, d.w};
        float l2t[4];
        #pragma unroll
        for (int j = 0; j < 4; ++j) {
            // single unsigned compare covers idx>=start && idx<end
            const bool in = (unsigned)(idx0 + j - start) < seglen;
            if (in) {
                float e = f_ex2((dv[j] + shift) * L2E);       // exp(x)
                l2t[j] = nInterval * f_lg2(1.f + e);          // <= 0
            } else {
                l2t[j] = 0.f;
            }
        }

        // thread-local inclusive prefix
        const float s0 = l2t[0];
        const float s1 = s0 + l2t[1];
        const float s2 = s1 + l2t[2];
        const float s3 = s2 + l2t[3];

        // warp scan of thread totals
        float inc = s3;
        #pragma unroll
        for (int off = 1; off < 32; off <<= 1) {
            float v = __shfl_up_sync(0xffffffffu, inc, off);
            if (lane >= off) inc += v;
        }
        const float excl = carry + (inc - s3);

        // transmittance samples; identical exponents => exact zero weights
        const float Pm1 = f_ex2(excl);
        const float P0  = f_ex2(excl + s0);
        const float P1  = f_ex2(excl + s1);
        const float P2  = f_ex2(excl + s2);
        const float P3  = f_ex2(excl + s3);

        const float w0 = Pm1 - P0;
        const float w1 = P0 - P1;
        const float w2 = P1 - P2;
        const float w3 = P2 - P3;

        // rgb layout: c0=(r0,g0,b0,r1) c1=(g1,b1,r2,g2) c2=(b2,r3,g3,b3)
        ar = fmaf(w0, c0.x, ar);  ag = fmaf(w0, c0.y, ag);  ab = fmaf(w0, c0.z, ab);
        ar = fmaf(w1, c0.w, ar);  ag = fmaf(w1, c1.x, ag);  ab = fmaf(w1, c1.y, ab);
        ar = fmaf(w2, c1.z, ar);  ag = fmaf(w2, c1.w, ag);  ab = fmaf(w2, c2.x, ab);
        ar = fmaf(w3, c2.y, ar);  ag = fmaf(w3, c2.z, ag);  ab = fmaf(w3, c2.w, ab);

        carry += __shfl_sync(0xffffffffu, inc, 31);
    }

    // warp reduction
    #pragma unroll
    for (int off = 16; off; off >>= 1) {
        ar += __shfl_xor_sync(0xffffffffu, ar, off);
        ag += __shfl_xor_sync(0xffffffffu, ag, off);
        ab += __shfl_xor_sync(0xffffffffu, ab, off);
    }

    if (lane == 0) {
        const float Tlast = f_ex2(carry);
        out[3 * warp + 0] = ar + Tlast * bg[0];
        out[3 * warp + 1] = ag + Tlast * bg[1];
        out[3 * warp + 2] = ab + Tlast * bg[2];
    }
}

extern "C" void kernel_launch(void* const* d_in, const int* in_sizes, int n_in,
                              void* d_out, int out_size) {
    const float* density    = (const float*)d_in[0];
    const float* rgb        = (const float*)d_in[1];
    const float* bg         = (const float*)d_in[2];
    const float* p_shift    = (const float*)d_in[3];
    const float* p_interval = (const float*)d_in[4];
    const int*   ray_id     = (const int*)d_in[5];

    const int M      = in_sizes[0];
    const int n_rays = out_size / 3;
    float* out = (float*)d_out;

    {
        const int nthreads16 = (M + 15) / 16;
        const int blocks = (nthreads16 + 255) / 256;
        build_offsets_vec16<<<blocks, 256>>>(ray_id, M, n_rays);
    }
    {
        const int blocks = (n_rays * 32 + 127) / 128;   // 4 rays per block
        composite_kernel<<<blocks, 128>>>(density, rgb, bg, p_shift,
                                          p_interval, out, n_rays);
    }
}

// round 15
// speedup vs baseline: 1.6477x; 1.4147x over previous
#include <cuda_runtime.h>

// DirectVoxGO volume rendering composite, R11: R10 + early ray termination.
//   log2(1-alpha_i) = -interval * log2(1 + exp(density_i + shift))
//   w_i = P_{i-1} - P_i,  P = 2^(per-ray inclusive prefix of log2(1-alpha))
//   out[r] = sum w_i rgb_i + P_last * bg
// When running log2(T) < -25, every remaining weight < 2^-25 (invisible at
// rel-tol 1e-3): warp-uniform break skips the rest of the ray's chunks.
//
// Kernel 1: offsets table, 16 elements/thread (4 x int4), prev via shfl.
// Kernel 2: one warp per ray, 4 samples/thread, all LDG.128, 38 regs,
//           128-thread blocks (13 blocks/SM -> 52 warps).

#define MAX_RAYS ((1 << 20))
__device__ int g_offsets[MAX_RAYS + 2];

__device__ __forceinline__ float f_ex2(float x) {
    float y; asm("ex2.approx.ftz.f32 %0, %1;" : "=f"(y) : "f"(x)); return y;
}
__device__ __forceinline__ float f_lg2(float x) {
    float y; asm("lg2.approx.ftz.f32 %0, %1;" : "=f"(y) : "f"(x)); return y;
}

// ---- Phase 1: offsets table, 16 elements per thread ----
__global__ void __launch_bounds__(256)
build_offsets_vec16(const int* __restrict__ ray_id, int M, int n_rays) {
    const int t  = blockIdx.x * blockDim.x + threadIdx.x;
    const int e0 = t * 16;
    const bool full = (e0 + 15 < M);

    int4 v0 = make_int4(0,0,0,0), v1 = v0, v2 = v0, v3 = v0;
    if (full) {
        const int4* p = reinterpret_cast<const int4*>(ray_id) + t * 4;
        v0 = p[0]; v1 = p[1]; v2 = p[2]; v3 = p[3];
    }
    const int prevw = __shfl_up_sync(0xffffffffu, v3.w, 1);

    if (e0 >= M) return;

    if (!full) {                          // scalar tail (generic-M safety)
        int prev = (e0 == 0) ? -1 : __ldg(&ray_id[e0 - 1]);
        for (int i = e0; i < M; ++i) {
            int cur = __ldg(&ray_id[i]);
            for (int r = prev + 1; r <= cur; ++r) g_offsets[r] = i;
            prev = cur;
        }
        for (int r = prev + 1; r <= n_rays; ++r) g_offsets[r] = M;
        return;
    }

    int prev;
    if ((threadIdx.x & 31) == 0 || e0 == 0)
        prev = (e0 == 0) ? -1 : __ldg(&ray_id[e0 - 1]);
    else
        prev = prevw;

    const int vals[16] = {v0.x, v0.y, v0.z, v0.w,  v1.x, v1.y, v1.z, v1.w,
                          v2.x, v2.y, v2.z, v2.w,  v3.x, v3.y, v3.z, v3.w};
    #pragma unroll
    for (int j = 0; j < 16; ++j) {
        const int cur = vals[j];
        if (cur != prev) {
            for (int r = prev + 1; r <= cur; ++r) g_offsets[r] = e0 + j;
        }
        prev = cur;
    }
    if (e0 + 15 == M - 1) {
        for (int r = prev + 1; r <= n_rays; ++r) g_offsets[r] = M;
    }
}

// ---- Phase 2: one warp per ray, 4 samples/thread, early termination ----
__global__ void __launch_bounds__(128)
composite_kernel(const float* __restrict__ density,
                 const float* __restrict__ rgb,
                 const float* __restrict__ bg,
                 const float* __restrict__ p_shift,
                 const float* __restrict__ p_interval,
                 float* __restrict__ out,
                 int n_rays) {
    const int warp = (blockIdx.x * blockDim.x + threadIdx.x) >> 5;
    const int lane = threadIdx.x & 31;
    if (warp >= n_rays) return;

    const int start = g_offsets[warp];
    const int end   = g_offsets[warp + 1];
    const unsigned seglen = (unsigned)(end - start);

    const float shift = *p_shift;
    const float nInterval = -(*p_interval);
    const float L2E = 1.4426950408889634f;

    float carry = 0.f;                 // running log2(T) at chunk entry
    float ar = 0.f, ag = 0.f, ab = 0.f;

    // aligned chunk base: idx0 = base + lane*4 is always 4-aligned -> LDG.128
    for (int base = (start & ~3); base < end; base += 128) {
        const int idx0 = base + lane * 4;
        const bool grp = (idx0 < end);

        float4 d  = make_float4(0.f, 0.f, 0.f, 0.f);
        float4 c0 = d, c1 = d, c2 = d;
        if (grp) {
            d  = *reinterpret_cast<const float4*>(density + idx0);
            const float* cbase = rgb + 3 * idx0;                  // 16B aligned
            c0 = *reinterpret_cast<const float4*>(cbase);
            c1 = *reinterpret_cast<const float4*>(cbase + 4);
            c2 = *reinterpret_cast<const float4*>(cbase + 8);
        }

        // per-element log2(1-alpha); 0 outside [start, end)
        float dv[4] = {d.x, d.y, d.z, d.w};
        float l2t[4];
        #pragma unroll
        for (int j = 0; j < 4; ++j) {
            // single unsigned compare covers idx>=start && idx<end
            const bool in = (unsigned)(idx0 + j - start) < seglen;
            if (in) {
                float e = f_ex2((dv[j] + shift) * L2E);       // exp(x)
                l2t[j] = nInterval * f_lg2(1.f + e);          // <= 0
            } else {
                l2t[j] = 0.f;
            }
        }

        // thread-local inclusive prefix
        const float s0 = l2t[0];
        const float s1 = s0 + l2t[1];
        const float s2 = s1 + l2t[2];
        const float s3 = s2 + l2t[3];

        // warp scan of thread totals
        float inc = s3;
        #pragma unroll
        for (int off = 1; off < 32; off <<= 1) {
            float v = __shfl_up_sync(0xffffffffu, inc, off);
            if (lane >= off) inc += v;
        }
        const float excl = carry + (inc - s3);

        // transmittance samples; identical exponents => exact zero weights
        const float Pm1 = f_ex2(excl);
        const float P0  = f_ex2(excl + s0);
        const float P1  = f_ex2(excl + s1);
        const float P2  = f_ex2(excl + s2);
        const float P3  = f_ex2(excl + s3);

        const float w0 = Pm1 - P0;
        const float w1 = P0 - P1;
        const float w2 = P1 - P2;
        const float w3 = P2 - P3;

        // rgb layout: c0=(r0,g0,b0,r1) c1=(g1,b1,r2,g2) c2=(b2,r3,g3,b3)
        ar = fmaf(w0, c0.x, ar);  ag = fmaf(w0, c0.y, ag);  ab = fmaf(w0, c0.z, ab);
        ar = fmaf(w1, c0.w, ar);  ag = fmaf(w1, c1.x, ag);  ab = fmaf(w1, c1.y, ab);
        ar = fmaf(w2, c1.z, ar);  ag = fmaf(w2, c1.w, ag);  ab = fmaf(w2, c2.x, ab);
        ar = fmaf(w3, c2.y, ar);  ag = fmaf(w3, c2.z, ag);  ab = fmaf(w3, c2.w, ab);

        carry += __shfl_sync(0xffffffffu, inc, 31);

        // early ray termination: all remaining weights < 2^-25 (warp-uniform)
        if (carry < -25.0f) break;
    }

    // warp reduction
    #pragma unroll
    for (int off = 16; off; off >>= 1) {
        ar += __shfl_xor_sync(0xffffffffu, ar, off);
        ag += __shfl_xor_sync(0xffffffffu, ag, off);
        ab += __shfl_xor_sync(0xffffffffu, ab, off);
    }

    if (lane == 0) {
        const float Tlast = f_ex2(carry);
        out[3 * warp + 0] = ar + Tlast * bg[0];
        out[3 * warp + 1] = ag + Tlast * bg[1];
        out[3 * warp + 2] = ab + Tlast * bg[2];
    }
}

extern "C" void kernel_launch(void* const* d_in, const int* in_sizes, int n_in,
                              void* d_out, int out_size) {
    const float* density    = (const float*)d_in[0];
    const float* rgb        = (const float*)d_in[1];
    const float* bg         = (const float*)d_in[2];
    const float* p_shift    = (const float*)d_in[3];
    const float* p_interval = (const float*)d_in[4];
    const int*   ray_id     = (const int*)d_in[5];

    const int M      = in_sizes[0];
    const int n_rays = out_size / 3;
    float* out = (float*)d_out;

    {
        const int nthreads16 = (M + 15) / 16;
        const int blocks = (nthreads16 + 255) / 256;
        build_offsets_vec16<<<blocks, 256>>>(ray_id, M, n_rays);
    }
    {
        const int blocks = (n_rays * 32 + 127) / 128;   // 4 rays per block
        composite_kernel<<<blocks, 128>>>(density, rgb, bg, p_shift,
                                          p_interval, out, n_rays);
    }
}

// round 16
// speedup vs baseline: 1.7173x; 1.0422x over previous
#include <cuda_runtime.h>

// DirectVoxGO volume rendering composite, R12: R11 + per-lane rgb skip.
//   log2(1-alpha_i) = -interval * log2(1 + exp(density_i + shift))
//   w_i = P_{i-1} - P_i,  P = 2^(per-ray inclusive prefix of log2(1-alpha))
//   out[r] = sum w_i rgb_i + P_last * bg
// Chunk-level early break when log2(T) < -25 (all later weights invisible);
// additionally, lanes whose entering log2(T) (excl) <= -25 skip their 3 rgb
// LDG.128s entirely -- their weights are < 2^-25 and contribute ~0.
//
// Kernel 1: offsets table, 16 elements/thread (4 x int4), prev via shfl.
// Kernel 2: one warp per ray, 4 samples/thread, 128-thread blocks.

#define MAX_RAYS ((1 << 20))
__device__ int g_offsets[MAX_RAYS + 2];

__device__ __forceinline__ float f_ex2(float x) {
    float y; asm("ex2.approx.ftz.f32 %0, %1;" : "=f"(y) : "f"(x)); return y;
}
__device__ __forceinline__ float f_lg2(float x) {
    float y; asm("lg2.approx.ftz.f32 %0, %1;" : "=f"(y) : "f"(x)); return y;
}

// ---- Phase 1: offsets table, 16 elements per thread ----
__global__ void __launch_bounds__(256)
build_offsets_vec16(const int* __restrict__ ray_id, int M, int n_rays) {
    const int t  = blockIdx.x * blockDim.x + threadIdx.x;
    const int e0 = t * 16;
    const bool full = (e0 + 15 < M);

    int4 v0 = make_int4(0,0,0,0), v1 = v0, v2 = v0, v3 = v0;
    if (full) {
        const int4* p = reinterpret_cast<const int4*>(ray_id) + t * 4;
        v0 = p[0]; v1 = p[1]; v2 = p[2]; v3 = p[3];
    }
    const int prevw = __shfl_up_sync(0xffffffffu, v3.w, 1);

    if (e0 >= M) return;

    if (!full) {                          // scalar tail (generic-M safety)
        int prev = (e0 == 0) ? -1 : __ldg(&ray_id[e0 - 1]);
        for (int i = e0; i < M; ++i) {
            int cur = __ldg(&ray_id[i]);
            for (int r = prev + 1; r <= cur; ++r) g_offsets[r] = i;
            prev = cur;
        }
        for (int r = prev + 1; r <= n_rays; ++r) g_offsets[r] = M;
        return;
    }

    int prev;
    if ((threadIdx.x & 31) == 0 || e0 == 0)
        prev = (e0 == 0) ? -1 : __ldg(&ray_id[e0 - 1]);
    else
        prev = prevw;

    const int vals[16] = {v0.x, v0.y, v0.z, v0.w,  v1.x, v1.y, v1.z, v1.w,
                          v2.x, v2.y, v2.z, v2.w,  v3.x, v3.y, v3.z, v3.w};
    #pragma unroll
    for (int j = 0; j < 16; ++j) {
        const int cur = vals[j];
        if (cur != prev) {
            for (int r = prev + 1; r <= cur; ++r) g_offsets[r] = e0 + j;
        }
        prev = cur;
    }
    if (e0 + 15 == M - 1) {
        for (int r = prev + 1; r <= n_rays; ++r) g_offsets[r] = M;
    }
}

// ---- Phase 2: one warp per ray, 4 samples/thread, lazy rgb ----
__global__ void __launch_bounds__(128)
composite_kernel(const float* __restrict__ density,
                 const float* __restrict__ rgb,
                 const float* __restrict__ bg,
                 const float* __restrict__ p_shift,
                 const float* __restrict__ p_interval,
                 float* __restrict__ out,
                 int n_rays) {
    const int warp = (blockIdx.x * blockDim.x + threadIdx.x) >> 5;
    const int lane = threadIdx.x & 31;
    if (warp >= n_rays) return;

    const int start = g_offsets[warp];
    const int end   = g_offsets[warp + 1];
    const unsigned seglen = (unsigned)(end - start);

    const float shift = *p_shift;
    const float nInterval = -(*p_interval);
    const float L2E = 1.4426950408889634f;

    float carry = 0.f;                 // running log2(T) at chunk entry
    float ar = 0.f, ag = 0.f, ab = 0.f;

    // aligned chunk base: idx0 = base + lane*4 is always 4-aligned -> LDG.128
    for (int base = (start & ~3); base < end; base += 128) {
        const int idx0 = base + lane * 4;
        const bool grp = (idx0 < end);

        float4 d = make_float4(0.f, 0.f, 0.f, 0.f);
        if (grp) d = *reinterpret_cast<const float4*>(density + idx0);

        // per-element log2(1-alpha); 0 outside [start, end)
        float dv[4] = {d.x, d.y, d.z, d.w};
        float l2t[4];
        #pragma unroll
        for (int j = 0; j < 4; ++j) {
            // single unsigned compare covers idx>=start && idx<end
            const bool in = (unsigned)(idx0 + j - start) < seglen;
            if (in) {
                float e = f_ex2((dv[j] + shift) * L2E);       // exp(x)
                l2t[j] = nInterval * f_lg2(1.f + e);          // <= 0
            } else {
                l2t[j] = 0.f;
            }
        }

        // thread-local inclusive prefix
        const float s0 = l2t[0];
        const float s1 = s0 + l2t[1];
        const float s2 = s1 + l2t[2];
        const float s3 = s2 + l2t[3];

        // warp scan of thread totals
        float inc = s3;
        #pragma unroll
        for (int off = 1; off < 32; off <<= 1) {
            float v = __shfl_up_sync(0xffffffffu, inc, off);
            if (lane >= off) inc += v;
        }
        const float excl = carry + (inc - s3);

        // lazy rgb: all weights in this lane <= 2^excl; skip loads if invisible
        float4 c0 = make_float4(0.f, 0.f, 0.f, 0.f), c1 = c0, c2 = c0;
        if (grp && excl > -25.0f) {
            const float* cbase = rgb + 3 * idx0;                  // 16B aligned
            c0 = *reinterpret_cast<const float4*>(cbase);
            c1 = *reinterpret_cast<const float4*>(cbase + 4);
            c2 = *reinterpret_cast<const float4*>(cbase + 8);
        }

        // transmittance samples; identical exponents => exact zero weights
        const float Pm1 = f_ex2(excl);
        const float P0  = f_ex2(excl + s0);
        const float P1  = f_ex2(excl + s1);
        const float P2  = f_ex2(excl + s2);
        const float P3  = f_ex2(excl + s3);

        const float w0 = Pm1 - P0;
        const float w1 = P0 - P1;
        const float w2 = P1 - P2;
        const float w3 = P2 - P3;

        // rgb layout: c0=(r0,g0,b0,r1) c1=(g1,b1,r2,g2) c2=(b2,r3,g3,b3)
        ar = fmaf(w0, c0.x, ar);  ag = fmaf(w0, c0.y, ag);  ab = fmaf(w0, c0.z, ab);
        ar = fmaf(w1, c0.w, ar);  ag = fmaf(w1, c1.x, ag);  ab = fmaf(w1, c1.y, ab);
        ar = fmaf(w2, c1.z, ar);  ag = fmaf(w2, c1.w, ag);  ab = fmaf(w2, c2.x, ab);
        ar = fmaf(w3, c2.y, ar);  ag = fmaf(w3, c2.z, ag);  ab = fmaf(w3, c2.w, ab);

        carry += __shfl_sync(0xffffffffu, inc, 31);

        // early ray termination: all remaining weights < 2^-25 (warp-uniform)
        if (carry < -25.0f) break;
    }

    // warp reduction
    #pragma unroll
    for (int off = 16; off; off >>= 1) {
        ar += __shfl_xor_sync(0xffffffffu, ar, off);
        ag += __shfl_xor_sync(0xffffffffu, ag, off);
        ab += __shfl_xor_sync(0xffffffffu, ab, off);
    }

    if (lane == 0) {
        const float Tlast = f_ex2(carry);
        out[3 * warp + 0] = ar + Tlast * bg[0];
        out[3 * warp + 1] = ag + Tlast * bg[1];
        out[3 * warp + 2] = ab + Tlast * bg[2];
    }
}

extern "C" void kernel_launch(void* const* d_in, const int* in_sizes, int n_in,
                              void* d_out, int out_size) {
    const float* density    = (const float*)d_in[0];
    const float* rgb        = (const float*)d_in[1];
    const float* bg         = (const float*)d_in[2];
    const float* p_shift    = (const float*)d_in[3];
    const float* p_interval = (const float*)d_in[4];
    const int*   ray_id     = (const int*)d_in[5];

    const int M      = in_sizes[0];
    const int n_rays = out_size / 3;
    float* out = (float*)d_out;

    {
        const int nthreads16 = (M + 15) / 16;
        const int blocks = (nthreads16 + 255) / 256;
        build_offsets_vec16<<<blocks, 256>>>(ray_id, M, n_rays);
    }
    {
        const int blocks = (n_rays * 32 + 127) / 128;   // 4 rays per block
        composite_kernel<<<blocks, 128>>>(density, rgb, bg, p_shift,
                                          p_interval, out, n_rays);
    }
}